// round 1
// baseline (speedup 1.0000x reference)
#include <cuda_runtime.h>

// Problem constants
#define NB 4
#define NL 2048
#define NE 1024
#define NH 8
#define ND 128
#define NM (NB * NL)   // 8192 rows
#define ATT_SCALE 0.08838834764831845f  // 1/sqrt(128)

// Scratch (static device globals — no runtime allocation allowed)
__device__ float g_Q[NB * NH * NL * ND];     // [b,h,l,d]
__device__ float g_K[NB * NH * NL * ND];
__device__ float g_V[NB * NH * NL * ND];
__device__ float g_ctx[NM * NE];             // [b*l, h*d]

// ---------------------------------------------------------------------------
// Tiled SGEMM: C = A[M=8192, K=1024] @ W[K=1024, N=1024]
// MODE 0: scatter output into [b,h,l,d] layout; MODE 1: plain row-major.
// Block tile 128x128, K-tile 8, 256 threads, 8x8 per-thread microtile.
// ---------------------------------------------------------------------------
template <int MODE>
__global__ __launch_bounds__(256, 2) void sgemm_kernel(
    const float* __restrict__ A, const float* __restrict__ W,
    float* __restrict__ C)
{
    const int K = 1024, N = 1024;
    __shared__ float As[8][128];   // transposed A tile: As[k][m]
    __shared__ float Bs[8][132];   // padded B tile:     Bs[k][n]

    const int tid = threadIdx.x;
    const int tx = tid & 15, ty = tid >> 4;
    const int m0 = blockIdx.y * 128, n0 = blockIdx.x * 128;

    const int arow  = tid >> 1, acol4 = (tid & 1) * 4;
    const int brow  = tid >> 5, bcol4 = (tid & 31) * 4;
    const float* Aptr = A + (size_t)(m0 + arow) * K + acol4;
    const float* Wptr = W + (size_t)brow * N + n0 + bcol4;

    float acc[8][8];
#pragma unroll
    for (int i = 0; i < 8; i++)
#pragma unroll
        for (int j = 0; j < 8; j++) acc[i][j] = 0.f;

    for (int k0 = 0; k0 < K; k0 += 8) {
        float4 av = *(const float4*)(Aptr + k0);
        float4 bv = *(const float4*)(Wptr + (size_t)k0 * N);
        As[acol4 + 0][arow] = av.x;
        As[acol4 + 1][arow] = av.y;
        As[acol4 + 2][arow] = av.z;
        As[acol4 + 3][arow] = av.w;
        *(float4*)&Bs[brow][bcol4] = bv;
        __syncthreads();

#pragma unroll
        for (int kk = 0; kk < 8; kk++) {
            float4 a0 = *(const float4*)&As[kk][ty * 8];
            float4 a1 = *(const float4*)&As[kk][ty * 8 + 4];
            float4 b0 = *(const float4*)&Bs[kk][tx * 8];
            float4 b1 = *(const float4*)&Bs[kk][tx * 8 + 4];
            float ra[8] = {a0.x, a0.y, a0.z, a0.w, a1.x, a1.y, a1.z, a1.w};
            float rb[8] = {b0.x, b0.y, b0.z, b0.w, b1.x, b1.y, b1.z, b1.w};
#pragma unroll
            for (int i = 0; i < 8; i++)
#pragma unroll
                for (int j = 0; j < 8; j++)
                    acc[i][j] += ra[i] * rb[j];
        }
        __syncthreads();
    }

#pragma unroll
    for (int i = 0; i < 8; i++) {
        const int m = m0 + ty * 8 + i;
#pragma unroll
        for (int j = 0; j < 8; j++) {
            const int n = n0 + tx * 8 + j;
            size_t idx;
            if (MODE == 0) {
                // m = b*2048 + l ; n = h*128 + d  ->  [b,h,l,d]
                idx = ((size_t)((m >> 11) * 8 + (n >> 7)) * 2048 + (m & 2047)) * 128
                      + (n & 127);
            } else {
                idx = (size_t)m * 1024 + n;
            }
            C[idx] = acc[i][j];
        }
    }
}

// ---------------------------------------------------------------------------
// Fused attention: per (b, h, 64-row q tile), flash-style online softmax.
// 256 threads = 16x16 grid. Scores: thread owns q rows ty*4+i, k cols tx+16j.
// PV: thread owns q rows ty*4+i, d cols tx*8..tx*8+7.
// ---------------------------------------------------------------------------
__global__ __launch_bounds__(256, 2) void attn_kernel(const unsigned char* __restrict__ mask)
{
    extern __shared__ float sm[];
    float* Qs = sm;                 // [64][128]           8192 floats
    float* Ks = sm + 64 * 128;      // K pitch 129 / V pitch 128 (reused) 64*132
    float* Ps = Ks + 64 * 132;      // [64][65]            4160 floats

    const int tid = threadIdx.x;
    const int tx = tid & 15, ty = tid >> 4;
    const int q0 = blockIdx.x * 64;
    const int h = blockIdx.y, b = blockIdx.z;
    const size_t bh = (size_t)(b * NH + h);
    const float* Qg = g_Q + bh * NL * ND;
    const float* Kg = g_K + bh * NL * ND;
    const float* Vg = g_V + bh * NL * ND;
    const unsigned char* mrow = mask + bh * (size_t)NL * NL;

    // Load Q tile (straight copy, float4)
#pragma unroll
    for (int i = 0; i < 8; i++) {
        int f = tid + i * 256;           // 0..2047 float4s
        int q = f >> 5, c4 = (f & 31) * 4;
        *(float4*)&Qs[q * 128 + c4] = *(const float4*)&Qg[(size_t)(q0 + q) * 128 + c4];
    }

    float m_i[4], l_i[4], O[4][8];
#pragma unroll
    for (int i = 0; i < 4; i++) {
        m_i[i] = -1e30f; l_i[i] = 0.f;
#pragma unroll
        for (int j = 0; j < 8; j++) O[i][j] = 0.f;
    }

    for (int k0 = 0; k0 < NL; k0 += 64) {
        __syncthreads();   // prior-tile V reads (and initial Q load) complete

        // Load K tile at pitch 129 (conflict-free strided reads later)
#pragma unroll
        for (int i = 0; i < 8; i++) {
            int f = tid + i * 256;
            int r = f >> 5, c4 = (f & 31) * 4;
            float4 v = *(const float4*)&Kg[(size_t)(k0 + r) * 128 + c4];
            Ks[r * 129 + c4 + 0] = v.x;
            Ks[r * 129 + c4 + 1] = v.y;
            Ks[r * 129 + c4 + 2] = v.z;
            Ks[r * 129 + c4 + 3] = v.w;
        }
        __syncthreads();

        // S = Q K^T
        float s[4][4];
#pragma unroll
        for (int i = 0; i < 4; i++)
#pragma unroll
            for (int j = 0; j < 4; j++) s[i][j] = 0.f;

#pragma unroll 4
        for (int d = 0; d < 128; d++) {
            float qv[4], kv[4];
#pragma unroll
            for (int i = 0; i < 4; i++) qv[i] = Qs[(ty * 4 + i) * 128 + d];
#pragma unroll
            for (int j = 0; j < 4; j++) kv[j] = Ks[(tx + 16 * j) * 129 + d];
#pragma unroll
            for (int i = 0; i < 4; i++)
#pragma unroll
                for (int j = 0; j < 4; j++)
                    s[i][j] += qv[i] * kv[j];
        }
        __syncthreads();   // all K reads done; buffer can become V

        // Load V tile (pitch 128, straight copy)
#pragma unroll
        for (int i = 0; i < 8; i++) {
            int f = tid + i * 256;
            int r = f >> 5, c4 = (f & 31) * 4;
            *(float4*)&Ks[r * 128 + c4] = *(const float4*)&Vg[(size_t)(k0 + r) * 128 + c4];
        }

        // Online softmax update + write P
#pragma unroll
        for (int i = 0; i < 4; i++) {
            const int qg = q0 + ty * 4 + i;
            float sv[4];
#pragma unroll
            for (int j = 0; j < 4; j++) {
                float x = s[i][j] * ATT_SCALE;
                const int kg = k0 + tx + 16 * j;
                if (mrow[(size_t)qg * NL + kg]) x = -1e9f;
                sv[j] = x;
            }
            float mx = fmaxf(fmaxf(sv[0], sv[1]), fmaxf(sv[2], sv[3]));
#pragma unroll
            for (int off = 8; off >= 1; off >>= 1)
                mx = fmaxf(mx, __shfl_xor_sync(0xffffffffu, mx, off, 16));
            const float mnew = fmaxf(m_i[i], mx);
            const float corr = __expf(m_i[i] - mnew);
            float sum = 0.f;
#pragma unroll
            for (int j = 0; j < 4; j++) {
                float p = __expf(sv[j] - mnew);
                Ps[(ty * 4 + i) * 65 + tx + 16 * j] = p;
                sum += p;
            }
#pragma unroll
            for (int off = 8; off >= 1; off >>= 1)
                sum += __shfl_xor_sync(0xffffffffu, sum, off, 16);
            l_i[i] = l_i[i] * corr + sum;
            m_i[i] = mnew;
#pragma unroll
            for (int j = 0; j < 8; j++) O[i][j] *= corr;
        }
        __syncthreads();   // V in smem + P written

        // O += P V
#pragma unroll 2
        for (int k = 0; k < 64; k++) {
            float pv[4];
#pragma unroll
            for (int i = 0; i < 4; i++) pv[i] = Ps[(ty * 4 + i) * 65 + k];
            float vv[8];
#pragma unroll
            for (int j = 0; j < 8; j++) vv[j] = Ks[k * 128 + tx * 8 + j];
#pragma unroll
            for (int i = 0; i < 4; i++)
#pragma unroll
                for (int j = 0; j < 8; j++)
                    O[i][j] += pv[i] * vv[j];
        }
    }

    // Normalize and write ctx in [b*l, h*128+d] layout
#pragma unroll
    for (int i = 0; i < 4; i++) {
        const float inv = 1.f / l_i[i];
        const int qg = q0 + ty * 4 + i;
        float* crow = g_ctx + ((size_t)(b * NL + qg)) * 1024 + h * 128 + tx * 8;
#pragma unroll
        for (int j = 0; j < 8; j++) crow[j] = O[i][j] * inv;
    }
}

// ---------------------------------------------------------------------------
extern "C" void kernel_launch(void* const* d_in, const int* in_sizes, int n_in,
                              void* d_out, int out_size)
{
    const float* qIn  = (const float*)d_in[0];
    const float* kvIn = (const float*)d_in[1];
    const unsigned char* mask = (const unsigned char*)d_in[2];
    const float* W_Q  = (const float*)d_in[3];
    const float* W_K  = (const float*)d_in[4];
    const float* W_V  = (const float*)d_in[5];
    const float* W_fc = (const float*)d_in[6];
    float* out = (float*)d_out;

    float *pQ, *pK, *pV, *pctx;
    cudaGetSymbolAddress((void**)&pQ, g_Q);
    cudaGetSymbolAddress((void**)&pK, g_K);
    cudaGetSymbolAddress((void**)&pV, g_V);
    cudaGetSymbolAddress((void**)&pctx, g_ctx);

    dim3 gg(8, 64);   // N/128, M/128
    sgemm_kernel<0><<<gg, 256>>>(qIn,  W_Q, pQ);
    sgemm_kernel<0><<<gg, 256>>>(kvIn, W_K, pK);
    sgemm_kernel<0><<<gg, 256>>>(kvIn, W_V, pV);

    const int smem = (64 * 128 + 64 * 132 + 64 * 65) * 4;  // 83200 B
    cudaFuncSetAttribute(attn_kernel, cudaFuncAttributeMaxDynamicSharedMemorySize, smem);
    attn_kernel<<<dim3(32, NH, NB), 256, smem>>>(mask);

    sgemm_kernel<1><<<gg, 256>>>(pctx, W_fc, out);
}

// round 3
// speedup vs baseline: 2.1033x; 2.1033x over previous
#include <cuda_runtime.h>
#include <cuda_bf16.h>
#include <mma.h>
#include <cstdint>

using namespace nvcuda;

// ---------------------------------------------------------------------------
// Problem constants
#define NB 4
#define NL 2048
#define NE 1024
#define NH 8
#define ND 128
#define NM (NB * NL)                       // 8192
#define ATT_SCALE 0.08838834764831845f     // 1/sqrt(128)

// ---------------------------------------------------------------------------
// cp.async helpers (sm_80 PTX — family-portable, compiles under compute_103)
// ---------------------------------------------------------------------------
__device__ __forceinline__ uint32_t smem_to_u32(const void* p) {
    uint32_t a;
    asm("{ .reg .u64 t; cvta.to.shared.u64 t, %1; cvt.u32.u64 %0, t; }"
        : "=r"(a) : "l"(p));
    return a;
}
#define CP_ASYNC_16(dst, src) \
    asm volatile("cp.async.cg.shared.global [%0], [%1], 16;" :: "r"(dst), "l"(src))
#define CP_COMMIT() asm volatile("cp.async.commit_group;" ::: "memory")
#define CP_WAIT(n)  asm volatile("cp.async.wait_group %0;" :: "n"(n) : "memory")

// ---------------------------------------------------------------------------
// Scratch (static device globals — no runtime allocation allowed)
// ---------------------------------------------------------------------------
__device__ __nv_bfloat16 g_Xqh[NM * NE], g_Xql[NM * NE];       // split qInputs
__device__ __nv_bfloat16 g_Xkh[NM * NE], g_Xkl[NM * NE];       // split kvInputs
__device__ __nv_bfloat16 g_WQh[NE * NE], g_WQl[NE * NE];       // W^T splits
__device__ __nv_bfloat16 g_WKh[NE * NE], g_WKl[NE * NE];
__device__ __nv_bfloat16 g_WVh[NE * NE], g_WVl[NE * NE];
__device__ __nv_bfloat16 g_WFh[NE * NE], g_WFl[NE * NE];
__device__ __nv_bfloat16 g_Qh[NM * NE], g_Ql[NM * NE];          // [b,h,l,d]
__device__ __nv_bfloat16 g_Kh[NM * NE], g_Kl[NM * NE];          // [b,h,l,d]
__device__ __nv_bfloat16 g_Vth[NM * NE], g_Vtl[NM * NE];        // [b,h,d,l]
__device__ float         g_S[(size_t)NB * NH * NL * NL];        // scores fp32
__device__ __nv_bfloat16 g_Ph[(size_t)NB * NH * NL * NL];       // P hi
__device__ __nv_bfloat16 g_Pl[(size_t)NB * NH * NL * NL];       // P lo
__device__ __nv_bfloat16 g_Ch[NM * NE], g_Cl[NM * NE];          // ctx split

// ---------------------------------------------------------------------------
// Elementwise fp32 -> (bf16 hi, bf16 lo) split
// ---------------------------------------------------------------------------
__global__ void split_kernel(const float* __restrict__ in,
                             __nv_bfloat16* __restrict__ hi,
                             __nv_bfloat16* __restrict__ lo, int n) {
    int i = blockIdx.x * 256 + threadIdx.x;
    if (i < n) {
        float x = in[i];
        __nv_bfloat16 h = __float2bfloat16(x);
        hi[i] = h;
        lo[i] = __float2bfloat16(x - __bfloat162float(h));
    }
}

// ---------------------------------------------------------------------------
// Transpose + split (for weights): out[c][r] = split(in[r][c])
// ---------------------------------------------------------------------------
__global__ void transpose_split_kernel(const float* __restrict__ in,
                                       __nv_bfloat16* __restrict__ oHi,
                                       __nv_bfloat16* __restrict__ oLo,
                                       int R, int Ccols) {
    __shared__ float t[32][33];
    const int c0 = blockIdx.x * 32, r0 = blockIdx.y * 32;
    const int x = threadIdx.x, y = threadIdx.y;
#pragma unroll
    for (int j = 0; j < 32; j += 8)
        t[y + j][x] = in[(size_t)(r0 + y + j) * Ccols + c0 + x];
    __syncthreads();
#pragma unroll
    for (int j = 0; j < 32; j += 8) {
        float v = t[x][y + j];
        __nv_bfloat16 h = __float2bfloat16(v);
        size_t o = (size_t)(c0 + y + j) * R + r0 + x;
        oHi[o] = h;
        oLo[o] = __float2bfloat16(v - __bfloat162float(h));
    }
}

// ---------------------------------------------------------------------------
// WMMA bf16x3 GEMM:  C[m][n] = sum_k A[m][k] * B[n][k]   (both K-major)
// 128x128 CTA tile, 8 warps (2x4), warp tile 64x32, K-chunk 32,
// cp.async 2-stage pipeline, smem pitch 40 (conflict-free ldmatrix).
// CMODE 0: fp32 C (ldc, batch strides)
// CMODE 1: split hi/lo scatter [b,h,l,d]      (m=b*2048+l, n=h*128+d)
// CMODE 2: split hi/lo scatter [b,h,d,l]      (transposed V)
// CMODE 3: split hi/lo row-major (ldc, batch strides)
// ---------------------------------------------------------------------------
#define TILE_B 10240              // 128*40*2 bytes per smem tile
#define CHUNK_B 40960             // 4 tiles

template <int CMODE>
__global__ __launch_bounds__(256) void gemm_kernel(
    const __nv_bfloat16* __restrict__ Ahi, const __nv_bfloat16* __restrict__ Alo,
    const __nv_bfloat16* __restrict__ Bhi, const __nv_bfloat16* __restrict__ Blo,
    float* __restrict__ C, __nv_bfloat16* __restrict__ Chi,
    __nv_bfloat16* __restrict__ Clo,
    int Kdim, int lda, int ldb, int ldc,
    long long sAh, long long sAl, long long sBh, long long sBl,
    long long sCh, long long sCl)
{
    extern __shared__ char smem[];
    const uint32_t sbase = smem_to_u32(smem);
    const int tid = threadIdx.x;
    const int wid = tid >> 5;
    const int wm = (wid & 1) * 64;    // warp m offset in tile
    const int wn = (wid >> 1) * 32;   // warp n offset in tile

    const long long zh = blockIdx.z >> 3, zl = blockIdx.z & 7;
    const __nv_bfloat16* Ah = Ahi + zh * sAh + zl * sAl;
    const __nv_bfloat16* Al = Alo + zh * sAh + zl * sAl;
    const __nv_bfloat16* Bh = Bhi + zh * sBh + zl * sBl;
    const __nv_bfloat16* Bl = Blo + zh * sBh + zl * sBl;
    const int m0 = blockIdx.y * 128, n0 = blockIdx.x * 128;

    wmma::fragment<wmma::accumulator, 16, 16, 16, float> acc[4][2];
#pragma unroll
    for (int mi = 0; mi < 4; mi++)
#pragma unroll
        for (int ni = 0; ni < 2; ni++) wmma::fill_fragment(acc[mi][ni], 0.f);

    const int nk = Kdim >> 5;

    // ---- chunk loader: 4 tiles of [128][32] bf16, smem pitch 40 ----
    auto load_chunk = [&](int kc, int buf) {
        const int k0 = kc << 5;
        const uint32_t dbase = sbase + buf * CHUNK_B;
        for (int i = tid; i < 2048; i += 256) {
            const int t = i >> 9;           // 0:Ah 1:Al 2:Bh 3:Bl
            const int r = (i >> 2) & 127;
            const int c = i & 3;            // 16-byte unit
            const __nv_bfloat16* g =
                (t == 0) ? Ah + (size_t)(m0 + r) * lda + k0 + c * 8 :
                (t == 1) ? Al + (size_t)(m0 + r) * lda + k0 + c * 8 :
                (t == 2) ? Bh + (size_t)(n0 + r) * ldb + k0 + c * 8 :
                           Bl + (size_t)(n0 + r) * ldb + k0 + c * 8;
            CP_ASYNC_16(dbase + t * TILE_B + r * 80 + c * 16, g);
        }
        CP_COMMIT();
    };

    load_chunk(0, 0);
    for (int kc = 0; kc < nk; kc++) {
        const int buf = kc & 1;
        if (kc + 1 < nk) {
            load_chunk(kc + 1, buf ^ 1);
            CP_WAIT(1);
        } else {
            CP_WAIT(0);
        }
        __syncthreads();

        const __nv_bfloat16* As_h = (const __nv_bfloat16*)(smem + buf * CHUNK_B);
        const __nv_bfloat16* As_l = (const __nv_bfloat16*)(smem + buf * CHUNK_B + TILE_B);
        const __nv_bfloat16* Bs_h = (const __nv_bfloat16*)(smem + buf * CHUNK_B + 2 * TILE_B);
        const __nv_bfloat16* Bs_l = (const __nv_bfloat16*)(smem + buf * CHUNK_B + 3 * TILE_B);

#pragma unroll
        for (int ks = 0; ks < 32; ks += 16) {
            wmma::fragment<wmma::matrix_a, 16, 16, 16, __nv_bfloat16, wmma::row_major> ah[4], al[4];
            wmma::fragment<wmma::matrix_b, 16, 16, 16, __nv_bfloat16, wmma::col_major> bh[2], bl[2];
#pragma unroll
            for (int mi = 0; mi < 4; mi++) {
                wmma::load_matrix_sync(ah[mi], As_h + (wm + mi * 16) * 40 + ks, 40);
                wmma::load_matrix_sync(al[mi], As_l + (wm + mi * 16) * 40 + ks, 40);
            }
#pragma unroll
            for (int ni = 0; ni < 2; ni++) {
                wmma::load_matrix_sync(bh[ni], Bs_h + (wn + ni * 16) * 40 + ks, 40);
                wmma::load_matrix_sync(bl[ni], Bs_l + (wn + ni * 16) * 40 + ks, 40);
            }
#pragma unroll
            for (int mi = 0; mi < 4; mi++)
#pragma unroll
                for (int ni = 0; ni < 2; ni++) {
                    wmma::mma_sync(acc[mi][ni], ah[mi], bh[ni], acc[mi][ni]);
                    wmma::mma_sync(acc[mi][ni], ah[mi], bl[ni], acc[mi][ni]);
                    wmma::mma_sync(acc[mi][ni], al[mi], bh[ni], acc[mi][ni]);
                }
        }
        __syncthreads();
    }

    // ---- epilogue: stage fp32 tile [128][132] in smem, then write out ----
    float* stage = (float*)smem;
#pragma unroll
    for (int mi = 0; mi < 4; mi++)
#pragma unroll
        for (int ni = 0; ni < 2; ni++)
            wmma::store_matrix_sync(stage + (wm + mi * 16) * 132 + wn + ni * 16,
                                    acc[mi][ni], 132, wmma::mem_row_major);
    __syncthreads();

    if (CMODE == 0) {
        float* Cp = C + zh * sCh + zl * sCl;
        for (int i = tid; i < 4096; i += 256) {
            const int r = i >> 5, c4 = (i & 31) * 4;
            float4 v = *(float4*)(stage + (size_t)r * 132 + c4);
            *(float4*)&Cp[(size_t)(m0 + r) * ldc + n0 + c4] = v;
        }
    } else if (CMODE == 1) {
        for (int i = tid; i < 16384; i += 256) {
            const int r = i >> 7, cc = i & 127;
            const int m = m0 + r, n = n0 + cc;
            float v = stage[(size_t)r * 132 + cc];
            __nv_bfloat16 h = __float2bfloat16(v);
            size_t idx = (((size_t)(m >> 11) * 8 + (n >> 7)) * 2048 + (m & 2047)) * 128
                         + (n & 127);
            Chi[idx] = h;
            Clo[idx] = __float2bfloat16(v - __bfloat162float(h));
        }
    } else if (CMODE == 2) {
        for (int i = tid; i < 16384; i += 256) {
            const int dl = i >> 7, ll = i & 127;   // consecutive tid -> consecutive l
            const int m = m0 + ll, n = n0 + dl;
            float v = stage[(size_t)ll * 132 + dl];
            __nv_bfloat16 h = __float2bfloat16(v);
            size_t idx = (((size_t)(m >> 11) * 8 + (n >> 7)) * 128 + (n & 127)) * 2048
                         + (m & 2047);
            Chi[idx] = h;
            Clo[idx] = __float2bfloat16(v - __bfloat162float(h));
        }
    } else {   // CMODE 3
        __nv_bfloat16* Ch = Chi + zh * sCh + zl * sCl;
        __nv_bfloat16* Cl = Clo + zh * sCh + zl * sCl;
        for (int i = tid; i < 16384; i += 256) {
            const int r = i >> 7, cc = i & 127;
            float v = stage[(size_t)r * 132 + cc];
            __nv_bfloat16 h = __float2bfloat16(v);
            size_t idx = (size_t)(m0 + r) * ldc + n0 + cc;
            Ch[idx] = h;
            Cl[idx] = __float2bfloat16(v - __bfloat162float(h));
        }
    }
}

// ---------------------------------------------------------------------------
// Masked softmax over rows of S; writes normalized P as bf16 hi/lo.
// ---------------------------------------------------------------------------
__global__ __launch_bounds__(256) void softmax_kernel(
    const float* __restrict__ S, const unsigned char* __restrict__ mask,
    __nv_bfloat16* __restrict__ Phi, __nv_bfloat16* __restrict__ Plo)
{
    __shared__ float buf[2048];
    __shared__ float red[8];
    const int tid = threadIdx.x;
    const size_t base = ((size_t)blockIdx.y * 2048 + blockIdx.x) * 2048;

    float mx = -1e30f;
    for (int i = tid; i < 2048; i += 256) {
        float x = S[base + i] * ATT_SCALE;
        if (mask[base + i]) x = -1e9f;
        buf[i] = x;
        mx = fmaxf(mx, x);
    }
#pragma unroll
    for (int o = 16; o; o >>= 1) mx = fmaxf(mx, __shfl_xor_sync(0xffffffffu, mx, o));
    if ((tid & 31) == 0) red[tid >> 5] = mx;
    __syncthreads();
    mx = red[0];
#pragma unroll
    for (int w = 1; w < 8; w++) mx = fmaxf(mx, red[w]);

    float sum = 0.f;
    for (int i = tid; i < 2048; i += 256) {
        float e = __expf(buf[i] - mx);
        buf[i] = e;
        sum += e;
    }
#pragma unroll
    for (int o = 16; o; o >>= 1) sum += __shfl_xor_sync(0xffffffffu, sum, o);
    __syncthreads();
    if ((tid & 31) == 0) red[tid >> 5] = sum;
    __syncthreads();
    sum = 0.f;
#pragma unroll
    for (int w = 0; w < 8; w++) sum += red[w];
    const float inv = 1.f / sum;

    for (int i = tid; i < 2048; i += 256) {
        float p = buf[i] * inv;
        __nv_bfloat16 h = __float2bfloat16(p);
        Phi[base + i] = h;
        Plo[base + i] = __float2bfloat16(p - __bfloat162float(h));
    }
}

// ---------------------------------------------------------------------------
extern "C" void kernel_launch(void* const* d_in, const int* in_sizes, int n_in,
                              void* d_out, int out_size)
{
    const float* qIn  = (const float*)d_in[0];
    const float* kvIn = (const float*)d_in[1];
    const unsigned char* mask = (const unsigned char*)d_in[2];
    const float* W_Q  = (const float*)d_in[3];
    const float* W_K  = (const float*)d_in[4];
    const float* W_V  = (const float*)d_in[5];
    const float* W_fc = (const float*)d_in[6];
    float* out = (float*)d_out;

    __nv_bfloat16 *pXqh, *pXql, *pXkh, *pXkl;
    __nv_bfloat16 *pWQh, *pWQl, *pWKh, *pWKl, *pWVh, *pWVl, *pWFh, *pWFl;
    __nv_bfloat16 *pQh, *pQl, *pKh, *pKl, *pVth, *pVtl, *pPh, *pPl, *pCh, *pCl;
    float *pS;
    cudaGetSymbolAddress((void**)&pXqh, g_Xqh);  cudaGetSymbolAddress((void**)&pXql, g_Xql);
    cudaGetSymbolAddress((void**)&pXkh, g_Xkh);  cudaGetSymbolAddress((void**)&pXkl, g_Xkl);
    cudaGetSymbolAddress((void**)&pWQh, g_WQh);  cudaGetSymbolAddress((void**)&pWQl, g_WQl);
    cudaGetSymbolAddress((void**)&pWKh, g_WKh);  cudaGetSymbolAddress((void**)&pWKl, g_WKl);
    cudaGetSymbolAddress((void**)&pWVh, g_WVh);  cudaGetSymbolAddress((void**)&pWVl, g_WVl);
    cudaGetSymbolAddress((void**)&pWFh, g_WFh);  cudaGetSymbolAddress((void**)&pWFl, g_WFl);
    cudaGetSymbolAddress((void**)&pQh,  g_Qh);   cudaGetSymbolAddress((void**)&pQl,  g_Ql);
    cudaGetSymbolAddress((void**)&pKh,  g_Kh);   cudaGetSymbolAddress((void**)&pKl,  g_Kl);
    cudaGetSymbolAddress((void**)&pVth, g_Vth);  cudaGetSymbolAddress((void**)&pVtl, g_Vtl);
    cudaGetSymbolAddress((void**)&pPh,  g_Ph);   cudaGetSymbolAddress((void**)&pPl,  g_Pl);
    cudaGetSymbolAddress((void**)&pCh,  g_Ch);   cudaGetSymbolAddress((void**)&pCl,  g_Cl);
    cudaGetSymbolAddress((void**)&pS,   g_S);

    const int NTOT = NM * NE;   // 8388608
    const int SMEM_GEMM = 2 * CHUNK_B;   // 81920
    cudaFuncSetAttribute(gemm_kernel<0>, cudaFuncAttributeMaxDynamicSharedMemorySize, SMEM_GEMM);
    cudaFuncSetAttribute(gemm_kernel<1>, cudaFuncAttributeMaxDynamicSharedMemorySize, SMEM_GEMM);
    cudaFuncSetAttribute(gemm_kernel<2>, cudaFuncAttributeMaxDynamicSharedMemorySize, SMEM_GEMM);
    cudaFuncSetAttribute(gemm_kernel<3>, cudaFuncAttributeMaxDynamicSharedMemorySize, SMEM_GEMM);

    // 1) split activations; transpose+split weights
    split_kernel<<<NTOT / 256, 256>>>(qIn,  pXqh, pXql, NTOT);
    split_kernel<<<NTOT / 256, 256>>>(kvIn, pXkh, pXkl, NTOT);
    transpose_split_kernel<<<dim3(32, 32), dim3(32, 8)>>>(W_Q,  pWQh, pWQl, 1024, 1024);
    transpose_split_kernel<<<dim3(32, 32), dim3(32, 8)>>>(W_K,  pWKh, pWKl, 1024, 1024);
    transpose_split_kernel<<<dim3(32, 32), dim3(32, 8)>>>(W_V,  pWVh, pWVl, 1024, 1024);
    transpose_split_kernel<<<dim3(32, 32), dim3(32, 8)>>>(W_fc, pWFh, pWFl, 1024, 1024);

    // 2) projections (epilogue writes split bf16 directly)
    gemm_kernel<1><<<dim3(8, 64, 1), 256, SMEM_GEMM>>>(
        pXqh, pXql, pWQh, pWQl, nullptr, pQh, pQl,
        1024, 1024, 1024, 0, 0, 0, 0, 0, 0, 0);
    gemm_kernel<1><<<dim3(8, 64, 1), 256, SMEM_GEMM>>>(
        pXkh, pXkl, pWKh, pWKl, nullptr, pKh, pKl,
        1024, 1024, 1024, 0, 0, 0, 0, 0, 0, 0);
    gemm_kernel<2><<<dim3(8, 64, 1), 256, SMEM_GEMM>>>(
        pXkh, pXkl, pWVh, pWVl, nullptr, pVth, pVtl,
        1024, 1024, 1024, 0, 0, 0, 0, 0, 0, 0);

    // 3) S = Q K^T  (batched over bh = 32)
    gemm_kernel<0><<<dim3(16, 16, 32), 256, SMEM_GEMM>>>(
        pQh, pQl, pKh, pKl, pS, nullptr, nullptr,
        128, 128, 128, 2048,
        (long long)8 * 2048 * 128, (long long)2048 * 128,
        (long long)8 * 2048 * 128, (long long)2048 * 128,
        (long long)8 * 2048 * 2048, (long long)2048 * 2048);

    // 4) softmax -> P hi/lo
    softmax_kernel<<<dim3(2048, 32), 256>>>(pS, mask, pPh, pPl);

    // 5) ctx = P V^T (batched), epilogue writes split ctx into [b*l, h*128+d]
    gemm_kernel<3><<<dim3(1, 16, 32), 256, SMEM_GEMM>>>(
        pPh, pPl, pVth, pVtl, nullptr, pCh, pCl,
        2048, 2048, 2048, 1024,
        (long long)8 * 2048 * 2048, (long long)2048 * 2048,
        (long long)8 * 128 * 2048,  (long long)128 * 2048,
        (long long)2048 * 1024,     (long long)128);

    // 6) out = ctx W_fc
    gemm_kernel<0><<<dim3(8, 64, 1), 256, SMEM_GEMM>>>(
        pCh, pCl, pWFh, pWFl, out, nullptr, nullptr,
        1024, 1024, 1024, 1024, 0, 0, 0, 0, 0, 0);
}